// round 12
// baseline (speedup 1.0000x reference)
#include <cuda_runtime.h>
#include <cuda_fp16.h>
#include <stdint.h>
#include <math.h>

#define DEVFN __device__ __forceinline__

static constexpr int NNODE = 4096, DIM = 128;
static constexpr int NU = 100000, NR = 32, NA = 5000;

// ---- device scratch ----
__device__ __align__(16) __half g_ua2e_h[NA * DIM];
__device__ __align__(16) float  g_R12T  [2 * NR * 256];
__device__ __align__(16) __half g_R12h  [64 * 258];       // fp16 R12 (stride 258)
__device__ __align__(16) float  g_selfA1[NNODE * DIM];
// B fragments, paired layout: uint4 per (ks, np, lane) = frags for nb=2np, 2np+1
__device__ __align__(16) uint2  g_FG1[2 * 16 * 16 * 32];  // K=256, two n-halves
__device__ __align__(16) uint2  g_FG2[16 * 16 * 32];      // K=256
__device__ __align__(16) uint2  g_FG3[8 * 16 * 32];       // K=128
__device__ __align__(16) uint2  g_FG4[8 * 16 * 32];       // K=128

// ---- smem layout (bytes) ----
static constexpr uint32_t OFF_B2S = 0, OFF_AB2 = 512, OFF_A3 = 1024, OFF_SA = 1536,
    OFF_LG = 2560, OFF_LGP = 3072, OFF_WGT = 5120, OFF_OUT = 5632, OFF_AB3 = 6656,
    OFF_RI = 6672, OFF_R12 = 7696, OFF_XB = 7696 + 33024;  // R12: 64x258 halfs
static constexpr int XS = 264;                        // X stride (halfs), K=256
static constexpr uint32_t SMEM_BYTES = OFF_XB + 128 * XS * 2;   // 108304

// ---- PTX helpers ----
DEVFN uint32_t smem_u32(const void* p) {
    uint32_t a;
    asm("{ .reg .u64 t; cvta.to.shared.u64 t, %1; cvt.u32.u64 %0, t; }" : "=r"(a) : "l"(p));
    return a;
}
DEVFN void ldm4(uint32_t* r, uint32_t a) {
    asm volatile("ldmatrix.sync.aligned.m8n8.x4.shared.b16 {%0,%1,%2,%3}, [%4];"
                 : "=r"(r[0]), "=r"(r[1]), "=r"(r[2]), "=r"(r[3]) : "r"(a));
}
DEVFN void mma16816(float* c, const uint32_t* a, uint32_t b0, uint32_t b1) {
    asm volatile("mma.sync.aligned.m16n8k16.row.col.f32.f16.f16.f32 "
                 "{%0,%1,%2,%3}, {%4,%5,%6,%7}, {%8,%9}, {%0,%1,%2,%3};"
                 : "+f"(c[0]), "+f"(c[1]), "+f"(c[2]), "+f"(c[3])
                 : "r"(a[0]), "r"(a[1]), "r"(a[2]), "r"(a[3]), "r"(b0), "r"(b1));
}

// single GEMM, paired-uint4 B fragments, register double-buffered prefetch
// 16 warps 4x4: mg 32 rows, ng 32 cols (4 nt)
template<int K>
DEVFN void gemm_tile(uint32_t aXbase, const uint2* __restrict__ F,
                     float (&acc)[2][4][4], int lane, int mg, int ng) {
    constexpr int KS = K / 16;
    uint32_t aA = aXbase + (uint32_t)((mg * 32 + ((lane >> 3) & 1) * 8 + (lane & 7)) * XS
                                      + (lane >> 4) * 8) * 2;
    const uint4* Fw = (const uint4*)F + (ng * 2) * 32 + lane;
    #pragma unroll
    for (int m = 0; m < 2; m++)
        #pragma unroll
        for (int n = 0; n < 4; n++)
            #pragma unroll
            for (int e = 0; e < 4; e++) acc[m][n][e] = 0.f;
    uint4 bf[2], bn[2];
    #pragma unroll
    for (int j = 0; j < 2; j++) bf[j] = __ldg(Fw + j * 32);
    #pragma unroll 1
    for (int ks = 0; ks < KS; ks++) {
        if (ks + 1 < KS) {
            #pragma unroll
            for (int j = 0; j < 2; j++) bn[j] = __ldg(Fw + (ks + 1) * 256 + j * 32);
        }
        uint32_t a0[4], a1[4];
        ldm4(a0, aA + ks * 32);
        ldm4(a1, aA + 16 * XS * 2 + ks * 32);
        #pragma unroll
        for (int j = 0; j < 2; j++) {
            mma16816(acc[0][2 * j],     a0, bf[j].x, bf[j].y);
            mma16816(acc[1][2 * j],     a1, bf[j].x, bf[j].y);
            mma16816(acc[0][2 * j + 1], a0, bf[j].z, bf[j].w);
            mma16816(acc[1][2 * j + 1], a1, bf[j].z, bf[j].w);
        }
        #pragma unroll
        for (int j = 0; j < 2; j++) bf[j] = bn[j];
    }
}

// dual GEMM (shared A fragments, two B tables), paired + prefetched
template<int K>
DEVFN void gemm_dual(uint32_t aXbase, const uint2* __restrict__ F0,
                     const uint2* __restrict__ F1,
                     float (&acc1)[2][4][4], float (&acc2)[2][4][4],
                     int lane, int mg, int ng) {
    constexpr int KS = K / 16;
    uint32_t aA = aXbase + (uint32_t)((mg * 32 + ((lane >> 3) & 1) * 8 + (lane & 7)) * XS
                                      + (lane >> 4) * 8) * 2;
    const uint4* Fw0 = (const uint4*)F0 + (ng * 2) * 32 + lane;
    const uint4* Fw1 = (const uint4*)F1 + (ng * 2) * 32 + lane;
    #pragma unroll
    for (int m = 0; m < 2; m++)
        #pragma unroll
        for (int n = 0; n < 4; n++)
            #pragma unroll
            for (int e = 0; e < 4; e++) { acc1[m][n][e] = 0.f; acc2[m][n][e] = 0.f; }
    uint4 bf0[2], bf1[2], bn0[2], bn1[2];
    #pragma unroll
    for (int j = 0; j < 2; j++) { bf0[j] = __ldg(Fw0 + j * 32); bf1[j] = __ldg(Fw1 + j * 32); }
    #pragma unroll 1
    for (int ks = 0; ks < KS; ks++) {
        if (ks + 1 < KS) {
            #pragma unroll
            for (int j = 0; j < 2; j++) {
                bn0[j] = __ldg(Fw0 + (ks + 1) * 256 + j * 32);
                bn1[j] = __ldg(Fw1 + (ks + 1) * 256 + j * 32);
            }
        }
        uint32_t a0[4], a1[4];
        ldm4(a0, aA + ks * 32);
        ldm4(a1, aA + 16 * XS * 2 + ks * 32);
        #pragma unroll
        for (int j = 0; j < 2; j++) {
            mma16816(acc1[0][2 * j],     a0, bf0[j].x, bf0[j].y);
            mma16816(acc1[1][2 * j],     a1, bf0[j].x, bf0[j].y);
            mma16816(acc1[0][2 * j + 1], a0, bf0[j].z, bf0[j].w);
            mma16816(acc1[1][2 * j + 1], a1, bf0[j].z, bf0[j].w);
            mma16816(acc2[0][2 * j],     a0, bf1[j].x, bf1[j].y);
            mma16816(acc2[1][2 * j],     a1, bf1[j].x, bf1[j].y);
            mma16816(acc2[0][2 * j + 1], a0, bf1[j].z, bf1[j].w);
            mma16816(acc2[1][2 * j + 1], a1, bf1[j].z, bf1[j].w);
        }
        #pragma unroll
        for (int j = 0; j < 2; j++) { bf0[j] = bn0[j]; bf1[j] = bn1[j]; }
    }
}

// ========== prepass 1: r12 (64 blk) || ua2e convert (128 blk) || selfA1 (512 blk) ==========
__global__ void k_prep1(const float* __restrict__ u2e, const float* __restrict__ ua2e,
                        const float* __restrict__ r2e, const float* __restrict__ W1,
                        const float* __restrict__ b1, const int* __restrict__ nodes,
                        const float* __restrict__ A1, const float* __restrict__ ab1) {
    __shared__ float sh[8 * 128];
    int b = blockIdx.x, tid = threadIdx.x;
    if (b < 64) {                       // r12: b = t*32+i
        int t = b >> 5, i = b & 31, c = tid;
        if (c < 128) sh[c] = r2e[i * 128 + c];
        __syncthreads();
        float acc = (t == 0) ? b1[c] : 0.f;
        #pragma unroll 4
        for (int k = 0; k < 128; k++) acc += sh[k] * W1[(t * 128 + k) * 256 + c];
        g_R12T[(t * 32 + i) * 256 + c] = acc;
    } else if (b < 192) {               // ua2e convert (2.56 MB), 128 blocks
        int st = 128 * 256, t0 = (b - 64) * 256 + tid;
        const float4* s2 = (const float4*)ua2e;  __half2* d2 = (__half2*)g_ua2e_h;
        for (int i = t0; i < NA * DIM / 4; i += st) {
            float4 v = s2[i];
            d2[2 * i] = __floats2half2_rn(v.x, v.y); d2[2 * i + 1] = __floats2half2_rn(v.z, v.w);
        }
    } else {                            // selfA1: warp-per-node, 512 blocks x 8 warps
        int w = tid >> 5, lane = tid & 31;
        int n = (b - 192) * 8 + w, nd = nodes[n];
        *(float4*)&sh[w * 128 + lane * 4] = *(const float4*)(u2e + (size_t)nd * 128 + lane * 4);
        __syncwarp();
        float4 acc = *(const float4*)(ab1 + lane * 4);
        const float4* A1b = (const float4*)(A1 + 16384) + lane;   // col block, stride 32 float4/k
        #pragma unroll 8
        for (int k = 0; k < 128; k++) {
            float s = sh[w * 128 + k];
            float4 a4 = __ldg(A1b + k * 32);
            acc.x += s * a4.x; acc.y += s * a4.y; acc.z += s * a4.z; acc.w += s * a4.w;
        }
        *(float4*)(g_selfA1 + (size_t)n * 128 + lane * 4) = acc;
    }
}

DEVFN uint32_t pack2(float a, float b) {
    __half2 h = __floats2half2_rn(a, b);
    return *(uint32_t*)&h;
}

// ================= prepass 2: pack B into paired MMA fragment order + R12h ==========
__global__ void k_pack(const float* __restrict__ W1, const float* __restrict__ W2,
                       const float* __restrict__ A1, const float* __restrict__ A2) {
    int id = blockIdx.x * 256 + threadIdx.x;   // 193 x 256 >= 49280
    if (id >= 32768) {                         // R12h fp16 table, stride 258
        int e = id - 32768;
        if (e < 64 * 258) {
            int r = e / 258, c = e % 258;
            g_R12h[e] = __float2half_rn(c < 256 ? g_R12T[r * 256 + c] : 0.f);
        }
        return;
    }
    int table, rem, h = 0;
    if (id < 16384)      { table = 1; h = id / 8192; rem = id % 8192; }
    else if (id < 24576) { table = 2; rem = id - 16384; }
    else if (id < 28672) { table = 3; rem = id - 24576; }
    else                 { table = 4; rem = id - 28672; }
    int lane = rem & 31, nb = (rem >> 5) & 15, ks = rem >> 9;
    int n = nb * 8 + (lane >> 2), k0 = ks * 16 + (lane & 3) * 2;
    float v[4];
    #pragma unroll
    for (int j = 0; j < 4; j++) {
        int k = k0 + (j >> 1) * 8 + (j & 1);
        float val;
        if (table == 1)      val = W1[(256 + k) * 256 + h * 128 + n];
        else if (table == 2) val = W2[k * 128 + n];
        else if (table == 3) val = A1[k * 128 + n];
        else                 val = A2[k * 128 + n];
        v[j] = val;
    }
    uint2 fr = make_uint2(pack2(v[0], v[1]), pack2(v[2], v[3]));
    int sidx = ks * 512 + (nb >> 1) * 64 + lane * 2 + (nb & 1);
    if (table == 1)      g_FG1[h * 8192 + sidx] = fr;
    else if (table == 2) g_FG2[sidx] = fr;
    else if (table == 3) g_FG3[sidx] = fr;
    else                 g_FG4[sidx] = fr;
}

// ================= main fused kernel =================
__global__ void __launch_bounds__(512, 1)
k_main(const int* __restrict__ prel, const int* __restrict__ pnbr,
       const int* __restrict__ attrs, const float* __restrict__ u2e,
       const float* __restrict__ b2, const float* __restrict__ ab2,
       const float* __restrict__ A3, const float* __restrict__ ab3,
       float* __restrict__ out) {
    extern __shared__ char sm[];
    const uint32_t sb = smem_u32(sm);
    const int tid = threadIdx.x, wid = tid >> 5, lane = tid & 31;
    const int mg = wid >> 2, ng = wid & 3;
    const int tile = blockIdx.x;

    float* b2s  = (float*)(sm + OFF_B2S);
    float* ab2s = (float*)(sm + OFF_AB2);
    float* A3s  = (float*)(sm + OFF_A3);
    float* SA   = (float*)(sm + OFF_SA);
    float* LG   = (float*)(sm + OFF_LG);
    float* LGP  = (float*)(sm + OFF_LGP);
    float* wgs  = (float*)(sm + OFF_WGT);
    float* OUTa = (float*)(sm + OFF_OUT);
    int2*  RIs  = (int2*)(sm + OFF_RI);
    __half* R12s = (__half*)(sm + OFF_R12);
    char*  XB   = sm + OFF_XB;
    const uint32_t aXB = sb + OFF_XB;

    if (tid < 128) { b2s[tid] = b2[tid]; ab2s[tid] = ab2[tid]; A3s[tid] = A3[tid]; }
    if (tid == 0) *(float*)(sm + OFF_AB3) = ab3[0];
    if (tid < 256) { SA[tid] = g_selfA1[(size_t)tile * 256 + tid]; OUTa[tid] = 0.f; }
    // copy R12h table to smem (33024 B = 2064 uint4)
    {
        const uint4* s = (const uint4*)g_R12h;
        uint4* d = (uint4*)(sm + OFF_R12);
        #pragma unroll
        for (int i = 0; i < 4; i++) d[tid + i * 512] = s[tid + i * 512];
        if (tid < 16) d[2048 + tid] = s[2048 + tid];
    }

    // ---- build X = [ne(128) | ae(128)], 4 thr/row; rel indices -> RIs ----
    {
        int row = tid >> 2, q = tid & 3, p = tile * 128 + row;
        char* XR = XB + row * (XS * 2);
        int nbr = pnbr[p];
        // ne: fp32 u2e gathered + converted inline (32 floats)
        const float4* s = (const float4*)(u2e + (size_t)nbr * 128 + q * 32);
        #pragma unroll
        for (int j = 0; j < 8; j++) {
            float4 v = s[j];
            *(__half2*)(XR + (q * 32 + j * 4) * 2)     = __floats2half2_rn(v.x, v.y);
            *(__half2*)(XR + (q * 32 + j * 4 + 2) * 2) = __floats2half2_rn(v.z, v.w);
        }
        int at[8];
        const int4* ap = (const int4*)(attrs + (size_t)p * 8);
        int4 a0v = ap[0], a1v = ap[1];
        at[0]=a0v.x; at[1]=a0v.y; at[2]=a0v.z; at[3]=a0v.w;
        at[4]=a1v.x; at[5]=a1v.y; at[6]=a1v.z; at[7]=a1v.w;
        // ae: 8 attrs x 32 halfs each, uint4 loads with next-attr prefetch
        float2 acc[16];
        #pragma unroll
        for (int i = 0; i < 16; i++) { acc[i].x = 0.f; acc[i].y = 0.f; }
        uint4 cur[4], nxt[4];
        {
            const uint4* qp = (const uint4*)(g_ua2e_h + (size_t)at[0] * 128) + q * 4;
            #pragma unroll
            for (int j = 0; j < 4; j++) cur[j] = __ldg(qp + j);
        }
        #pragma unroll 1
        for (int a = 0; a < 8; a++) {
            if (a + 1 < 8) {
                const uint4* qp = (const uint4*)(g_ua2e_h + (size_t)at[a + 1] * 128) + q * 4;
                #pragma unroll
                for (int j = 0; j < 4; j++) nxt[j] = __ldg(qp + j);
            }
            #pragma unroll
            for (int j = 0; j < 4; j++) {
                float2 f0 = __half22float2(*(__half2*)&cur[j].x);
                float2 f1 = __half22float2(*(__half2*)&cur[j].y);
                float2 f2 = __half22float2(*(__half2*)&cur[j].z);
                float2 f3 = __half22float2(*(__half2*)&cur[j].w);
                acc[j * 4 + 0].x += f0.x; acc[j * 4 + 0].y += f0.y;
                acc[j * 4 + 1].x += f1.x; acc[j * 4 + 1].y += f1.y;
                acc[j * 4 + 2].x += f2.x; acc[j * 4 + 2].y += f2.y;
                acc[j * 4 + 3].x += f3.x; acc[j * 4 + 3].y += f3.y;
            }
            #pragma unroll
            for (int j = 0; j < 4; j++) cur[j] = nxt[j];
        }
        #pragma unroll
        for (int i = 0; i < 16; i++)
            *(__half2*)(XR + (128 + q * 32 + 2 * i) * 2) = __floats2half2_rn(acc[i].x, acc[i].y);
        if (q == 0) {
            int r0 = prel[p * 2], r1 = prel[p * 2 + 1];
            RIs[row] = make_int2(r0, 32 + r1);
        }
    }
    __syncthreads();

    float acc1[2][4][4], acc2[2][4][4];

    // G1 (dual): X @ W1' -> h1 cols 0-127 (acc1), 128-255 (acc2)
    gemm_dual<256>(aXB, g_FG1, g_FG1 + 8192, acc1, acc2, lane, mg, ng);
    __syncthreads();

    // epilogue1: h1 = relu(acc + R12[r0] + R12[32+r1]) -> fp16 XB cols 0-255
    #pragma unroll
    for (int mf = 0; mf < 2; mf++) {
        int row = mg * 32 + mf * 16 + (lane >> 2);
        int2 ra = RIs[row], rb = RIs[row + 8];
        const __half* Ra0 = R12s + ra.x * 258;
        const __half* Ra1 = R12s + ra.y * 258;
        const __half* Rb0 = R12s + rb.x * 258;
        const __half* Rb1 = R12s + rb.y * 258;
        #pragma unroll
        for (int nt = 0; nt < 4; nt++) {
            int col = ng * 32 + nt * 8 + (lane & 3) * 2;
            float2 pa0 = __half22float2(*(const __half2*)(Ra0 + col));
            float2 pa1 = __half22float2(*(const __half2*)(Ra1 + col));
            float2 pb0 = __half22float2(*(const __half2*)(Rb0 + col));
            float2 pb1 = __half22float2(*(const __half2*)(Rb1 + col));
            *(__half2*)(XB + (row * XS + col) * 2) = __floats2half2_rn(
                fmaxf(acc1[mf][nt][0] + pa0.x + pa1.x, 0.f),
                fmaxf(acc1[mf][nt][1] + pa0.y + pa1.y, 0.f));
            *(__half2*)(XB + ((row + 8) * XS + col) * 2) = __floats2half2_rn(
                fmaxf(acc1[mf][nt][2] + pb0.x + pb1.x, 0.f),
                fmaxf(acc1[mf][nt][3] + pb0.y + pb1.y, 0.f));
            float2 qa0 = __half22float2(*(const __half2*)(Ra0 + col + 128));
            float2 qa1 = __half22float2(*(const __half2*)(Ra1 + col + 128));
            float2 qb0 = __half22float2(*(const __half2*)(Rb0 + col + 128));
            float2 qb1 = __half22float2(*(const __half2*)(Rb1 + col + 128));
            *(__half2*)(XB + (row * XS + col + 128) * 2) = __floats2half2_rn(
                fmaxf(acc2[mf][nt][0] + qa0.x + qa1.x, 0.f),
                fmaxf(acc2[mf][nt][1] + qa0.y + qa1.y, 0.f));
            *(__half2*)(XB + ((row + 8) * XS + col + 128) * 2) = __floats2half2_rn(
                fmaxf(acc2[mf][nt][2] + qb0.x + qb1.x, 0.f),
                fmaxf(acc2[mf][nt][3] + qb0.y + qb1.y, 0.f));
        }
    }
    __syncthreads();
    // G2: h1 @ W2' -> acc2 = h pre-bias (fp32, kept in regs)
    gemm_tile<256>(aXB, g_FG2, acc2, lane, mg, ng);
    __syncthreads();

    // epilogue2: h = relu(acc2 + b2); keep fp32 in acc2, write fp16 XB cols 0-127
    #pragma unroll
    for (int mf = 0; mf < 2; mf++) {
        int row = mg * 32 + mf * 16 + (lane >> 2);
        #pragma unroll
        for (int nt = 0; nt < 4; nt++) {
            int col = ng * 32 + nt * 8 + (lane & 3) * 2;
            float v0 = fmaxf(acc2[mf][nt][0] + b2s[col],     0.f);
            float v1 = fmaxf(acc2[mf][nt][1] + b2s[col + 1], 0.f);
            float v2 = fmaxf(acc2[mf][nt][2] + b2s[col],     0.f);
            float v3 = fmaxf(acc2[mf][nt][3] + b2s[col + 1], 0.f);
            acc2[mf][nt][0] = v0; acc2[mf][nt][1] = v1;
            acc2[mf][nt][2] = v2; acc2[mf][nt][3] = v3;
            *(__half2*)(XB + (row * XS + col) * 2)       = __floats2half2_rn(v0, v1);
            *(__half2*)(XB + ((row + 8) * XS + col) * 2) = __floats2half2_rn(v2, v3);
        }
    }
    __syncthreads();
    // G3: h @ A1top -> acc1
    gemm_tile<128>(aXB, g_FG3, acc1, lane, mg, ng);

    // epilogue3: a1 = relu(acc1 + selfA1[node]) -> fp16 XB cols 128-255
    {
        int node = mg >> 1;
        #pragma unroll
        for (int mf = 0; mf < 2; mf++) {
            int row = mg * 32 + mf * 16 + (lane >> 2);
            #pragma unroll
            for (int nt = 0; nt < 4; nt++) {
                int col = ng * 32 + nt * 8 + (lane & 3) * 2;
                float s0 = SA[node * 128 + col], s1 = SA[node * 128 + col + 1];
                *(__half2*)(XB + (row * XS + col + 128) * 2) =
                    __floats2half2_rn(fmaxf(acc1[mf][nt][0] + s0, 0.f),
                                      fmaxf(acc1[mf][nt][1] + s1, 0.f));
                *(__half2*)(XB + ((row + 8) * XS + col + 128) * 2) =
                    __floats2half2_rn(fmaxf(acc1[mf][nt][2] + s0, 0.f),
                                      fmaxf(acc1[mf][nt][3] + s1, 0.f));
            }
        }
    }
    __syncthreads();
    // G4: a1 @ A2 -> acc1
    gemm_tile<128>(aXB + 256, g_FG4, acc1, lane, mg, ng);

    // epilogue4: a2 = relu(acc1 + ab2); logit partials
    {
        float lp[4] = {0.f, 0.f, 0.f, 0.f};
        #pragma unroll
        for (int mf = 0; mf < 2; mf++)
            #pragma unroll
            for (int nt = 0; nt < 4; nt++) {
                int col = ng * 32 + nt * 8 + (lane & 3) * 2;
                float a30 = A3s[col], a31 = A3s[col + 1];
                float c0 = ab2s[col], c1 = ab2s[col + 1];
                lp[mf * 2 + 0] += fmaxf(acc1[mf][nt][0] + c0, 0.f) * a30
                                + fmaxf(acc1[mf][nt][1] + c1, 0.f) * a31;
                lp[mf * 2 + 1] += fmaxf(acc1[mf][nt][2] + c0, 0.f) * a30
                                + fmaxf(acc1[mf][nt][3] + c1, 0.f) * a31;
            }
        #pragma unroll
        for (int j = 0; j < 4; j++) {
            lp[j] += __shfl_xor_sync(0xffffffffu, lp[j], 1);
            lp[j] += __shfl_xor_sync(0xffffffffu, lp[j], 2);
        }
        if ((lane & 3) == 0) {
            int rbase = mg * 32 + (lane >> 2);
            #pragma unroll
            for (int j = 0; j < 4; j++)
                LGP[ng * 128 + rbase + j * 8] = lp[j];
        }
    }
    __syncthreads();
    if (tid < 128)
        LG[tid] = LGP[tid] + LGP[128 + tid] + LGP[256 + tid] + LGP[384 + tid]
                + *(float*)(sm + OFF_AB3);
    __syncthreads();
    if (wid < 2) {   // softmax per node over its 64 logits
        float a = LG[wid * 64 + lane], b = LG[wid * 64 + 32 + lane];
        float m = fmaxf(a, b);
        #pragma unroll
        for (int o = 16; o; o >>= 1) m = fmaxf(m, __shfl_xor_sync(0xffffffffu, m, o));
        float e1 = __expf(a - m), e2 = __expf(b - m), s = e1 + e2;
        #pragma unroll
        for (int o = 16; o; o >>= 1) s += __shfl_xor_sync(0xffffffffu, s, o);
        wgs[wid * 64 + lane] = e1 / s; wgs[wid * 64 + 32 + lane] = e2 / s;
    }
    __syncthreads();

    // weighted reduce: out[node][col] = sum_r wgs[r] * h[r][col]  (h fp32 in acc2)
    {
        float p[8];
        #pragma unroll
        for (int i = 0; i < 8; i++) p[i] = 0.f;
        #pragma unroll
        for (int mf = 0; mf < 2; mf++) {
            int r0 = mg * 32 + mf * 16 + (lane >> 2);
            float w0 = wgs[r0], w1 = wgs[r0 + 8];
            #pragma unroll
            for (int nt = 0; nt < 4; nt++) {
                p[nt * 2 + 0] += w0 * acc2[mf][nt][0] + w1 * acc2[mf][nt][2];
                p[nt * 2 + 1] += w0 * acc2[mf][nt][1] + w1 * acc2[mf][nt][3];
            }
        }
        #pragma unroll
        for (int i = 0; i < 8; i++) {
            p[i] += __shfl_xor_sync(0xffffffffu, p[i], 4);
            p[i] += __shfl_xor_sync(0xffffffffu, p[i], 8);
            p[i] += __shfl_xor_sync(0xffffffffu, p[i], 16);
        }
        if (lane < 4) {
            int node = mg >> 1;
            #pragma unroll
            for (int i = 0; i < 8; i++) {
                int col = ng * 32 + (i >> 1) * 8 + lane * 2 + (i & 1);
                atomicAdd(&OUTa[node * 128 + col], p[i]);
            }
        }
    }
    __syncthreads();
    if (tid < 256) out[(size_t)tile * 256 + tid] = OUTa[tid];
}

// ================= launch =================
extern "C" void kernel_launch(void* const* d_in, const int* in_sizes, int n_in,
                              void* d_out, int out_size) {
    const int*   nodes = (const int*)  d_in[0];
    const int*   prel  = (const int*)  d_in[1];
    const int*   pnbr  = (const int*)  d_in[2];
    const int*   attrs = (const int*)  d_in[3];
    const float* u2e   = (const float*)d_in[4];
    const float* r2e   = (const float*)d_in[5];
    const float* ua2e  = (const float*)d_in[6];
    const float* W1    = (const float*)d_in[7];
    const float* b1    = (const float*)d_in[8];
    const float* W2    = (const float*)d_in[9];
    const float* b2    = (const float*)d_in[10];
    const float* A1    = (const float*)d_in[11];
    const float* ab1   = (const float*)d_in[12];
    const float* A2    = (const float*)d_in[13];
    const float* ab2   = (const float*)d_in[14];
    const float* A3    = (const float*)d_in[15];
    const float* ab3   = (const float*)d_in[16];
    float* out = (float*)d_out;

    cudaFuncSetAttribute(k_main, cudaFuncAttributeMaxDynamicSharedMemorySize, (int)SMEM_BYTES);

    k_prep1<<<704, 256>>>(u2e, ua2e, r2e, W1, b1, nodes, A1, ab1);
    k_pack<<<193, 256>>>(W1, W2, A1, A2);
    k_main<<<2048, 512, SMEM_BYTES>>>(prel, pnbr, attrs, u2e, b2, ab2, A3, ab3, out);
}

// round 13
// speedup vs baseline: 1.0036x; 1.0036x over previous
#include <cuda_runtime.h>
#include <cuda_fp16.h>
#include <stdint.h>
#include <math.h>

#define DEVFN __device__ __forceinline__

static constexpr int NNODE = 4096, DIM = 128;
static constexpr int NU = 100000, NR = 32, NA = 5000;

// ---- device scratch ----
__device__ __align__(16) __half g_ua2e_h[NA * DIM];
__device__ __align__(16) __half g_R12h  [64 * 258];       // fp16 R12 (stride 258)
__device__ __align__(16) float  g_selfA1[NNODE * DIM];
// B fragments, paired layout: uint4 per (ks, np, lane) = frags for nb=2np, 2np+1
__device__ __align__(16) uint2  g_FG1[2 * 16 * 16 * 32];  // K=256, two n-halves
__device__ __align__(16) uint2  g_FG2[16 * 16 * 32];      // K=256
__device__ __align__(16) uint2  g_FG3[8 * 16 * 32];       // K=128
__device__ __align__(16) uint2  g_FG4[8 * 16 * 32];       // K=128

// ---- smem layout (bytes) ----
static constexpr uint32_t OFF_B2S = 0, OFF_AB2 = 512, OFF_A3 = 1024, OFF_SA = 1536,
    OFF_LG = 2560, OFF_LGP = 3072, OFF_WGT = 5120, OFF_OUT = 5632, OFF_AB3 = 6656,
    OFF_RI = 6672, OFF_R12 = 7696, OFF_XB = 7696 + 33024;  // R12: 64x258 halfs
static constexpr int XS = 264;                        // X stride (halfs), K=256
static constexpr uint32_t SMEM_BYTES = OFF_XB + 128 * XS * 2;   // 108304

// ---- PTX helpers ----
DEVFN uint32_t smem_u32(const void* p) {
    uint32_t a;
    asm("{ .reg .u64 t; cvta.to.shared.u64 t, %1; cvt.u32.u64 %0, t; }" : "=r"(a) : "l"(p));
    return a;
}
DEVFN void ldm4(uint32_t* r, uint32_t a) {
    asm volatile("ldmatrix.sync.aligned.m8n8.x4.shared.b16 {%0,%1,%2,%3}, [%4];"
                 : "=r"(r[0]), "=r"(r[1]), "=r"(r[2]), "=r"(r[3]) : "r"(a));
}
DEVFN void mma16816(float* c, const uint32_t* a, uint32_t b0, uint32_t b1) {
    asm volatile("mma.sync.aligned.m16n8k16.row.col.f32.f16.f16.f32 "
                 "{%0,%1,%2,%3}, {%4,%5,%6,%7}, {%8,%9}, {%0,%1,%2,%3};"
                 : "+f"(c[0]), "+f"(c[1]), "+f"(c[2]), "+f"(c[3])
                 : "r"(a[0]), "r"(a[1]), "r"(a[2]), "r"(a[3]), "r"(b0), "r"(b1));
}

// single GEMM, paired-uint4 B fragments, register double-buffered prefetch
// 16 warps 4x4: mg 32 rows, ng 32 cols (4 nt)
template<int K>
DEVFN void gemm_tile(uint32_t aXbase, const uint2* __restrict__ F,
                     float (&acc)[2][4][4], int lane, int mg, int ng) {
    constexpr int KS = K / 16;
    uint32_t aA = aXbase + (uint32_t)((mg * 32 + ((lane >> 3) & 1) * 8 + (lane & 7)) * XS
                                      + (lane >> 4) * 8) * 2;
    const uint4* Fw = (const uint4*)F + (ng * 2) * 32 + lane;
    #pragma unroll
    for (int m = 0; m < 2; m++)
        #pragma unroll
        for (int n = 0; n < 4; n++)
            #pragma unroll
            for (int e = 0; e < 4; e++) acc[m][n][e] = 0.f;
    uint4 bf[2], bn[2];
    #pragma unroll
    for (int j = 0; j < 2; j++) bf[j] = __ldg(Fw + j * 32);
    #pragma unroll 1
    for (int ks = 0; ks < KS; ks++) {
        if (ks + 1 < KS) {
            #pragma unroll
            for (int j = 0; j < 2; j++) bn[j] = __ldg(Fw + (ks + 1) * 256 + j * 32);
        }
        uint32_t a0[4], a1[4];
        ldm4(a0, aA + ks * 32);
        ldm4(a1, aA + 16 * XS * 2 + ks * 32);
        #pragma unroll
        for (int j = 0; j < 2; j++) {
            mma16816(acc[0][2 * j],     a0, bf[j].x, bf[j].y);
            mma16816(acc[1][2 * j],     a1, bf[j].x, bf[j].y);
            mma16816(acc[0][2 * j + 1], a0, bf[j].z, bf[j].w);
            mma16816(acc[1][2 * j + 1], a1, bf[j].z, bf[j].w);
        }
        #pragma unroll
        for (int j = 0; j < 2; j++) bf[j] = bn[j];
    }
}

// dual GEMM (shared A fragments, two B tables), paired + prefetched
template<int K>
DEVFN void gemm_dual(uint32_t aXbase, const uint2* __restrict__ F0,
                     const uint2* __restrict__ F1,
                     float (&acc1)[2][4][4], float (&acc2)[2][4][4],
                     int lane, int mg, int ng) {
    constexpr int KS = K / 16;
    uint32_t aA = aXbase + (uint32_t)((mg * 32 + ((lane >> 3) & 1) * 8 + (lane & 7)) * XS
                                      + (lane >> 4) * 8) * 2;
    const uint4* Fw0 = (const uint4*)F0 + (ng * 2) * 32 + lane;
    const uint4* Fw1 = (const uint4*)F1 + (ng * 2) * 32 + lane;
    #pragma unroll
    for (int m = 0; m < 2; m++)
        #pragma unroll
        for (int n = 0; n < 4; n++)
            #pragma unroll
            for (int e = 0; e < 4; e++) { acc1[m][n][e] = 0.f; acc2[m][n][e] = 0.f; }
    uint4 bf0[2], bf1[2], bn0[2], bn1[2];
    #pragma unroll
    for (int j = 0; j < 2; j++) { bf0[j] = __ldg(Fw0 + j * 32); bf1[j] = __ldg(Fw1 + j * 32); }
    #pragma unroll 1
    for (int ks = 0; ks < KS; ks++) {
        if (ks + 1 < KS) {
            #pragma unroll
            for (int j = 0; j < 2; j++) {
                bn0[j] = __ldg(Fw0 + (ks + 1) * 256 + j * 32);
                bn1[j] = __ldg(Fw1 + (ks + 1) * 256 + j * 32);
            }
        }
        uint32_t a0[4], a1[4];
        ldm4(a0, aA + ks * 32);
        ldm4(a1, aA + 16 * XS * 2 + ks * 32);
        #pragma unroll
        for (int j = 0; j < 2; j++) {
            mma16816(acc1[0][2 * j],     a0, bf0[j].x, bf0[j].y);
            mma16816(acc1[1][2 * j],     a1, bf0[j].x, bf0[j].y);
            mma16816(acc1[0][2 * j + 1], a0, bf0[j].z, bf0[j].w);
            mma16816(acc1[1][2 * j + 1], a1, bf0[j].z, bf0[j].w);
            mma16816(acc2[0][2 * j],     a0, bf1[j].x, bf1[j].y);
            mma16816(acc2[1][2 * j],     a1, bf1[j].x, bf1[j].y);
            mma16816(acc2[0][2 * j + 1], a0, bf1[j].z, bf1[j].w);
            mma16816(acc2[1][2 * j + 1], a1, bf1[j].z, bf1[j].w);
        }
        #pragma unroll
        for (int j = 0; j < 2; j++) { bf0[j] = bn0[j]; bf1[j] = bn1[j]; }
    }
}

DEVFN uint32_t pack2(float a, float b) {
    __half2 h = __floats2half2_rn(a, b);
    return *(uint32_t*)&h;
}

// ===== SINGLE prepass kernel: r12+R12h (64) || ua2e cvt (128) || selfA1 (512) || pack (128) =====
__global__ void k_prep(const float* __restrict__ u2e, const float* __restrict__ ua2e,
                       const float* __restrict__ r2e, const float* __restrict__ W1,
                       const float* __restrict__ b1, const int* __restrict__ nodes,
                       const float* __restrict__ A1, const float* __restrict__ ab1,
                       const float* __restrict__ W2, const float* __restrict__ A2) {
    __shared__ float sh[8 * 128];
    int b = blockIdx.x, tid = threadIdx.x;
    if (b < 64) {                       // r12: b = t*32+i -> writes fp16 R12h row directly
        int t = b >> 5, i = b & 31, c = tid;
        if (c < 128) sh[c] = r2e[i * 128 + c];
        __syncthreads();
        float acc = (t == 0) ? b1[c] : 0.f;
        #pragma unroll 4
        for (int k = 0; k < 128; k++) acc += sh[k] * W1[(t * 128 + k) * 256 + c];
        int r = t * 32 + i;
        g_R12h[r * 258 + c] = __float2half_rn(acc);
        if (c < 2) g_R12h[r * 258 + 256 + c] = __ushort_as_half((unsigned short)0);
    } else if (b < 192) {               // ua2e convert (2.56 MB), 128 blocks
        int st = 128 * 256, t0 = (b - 64) * 256 + tid;
        const float4* s2 = (const float4*)ua2e;  __half2* d2 = (__half2*)g_ua2e_h;
        for (int i = t0; i < NA * DIM / 4; i += st) {
            float4 v = s2[i];
            d2[2 * i] = __floats2half2_rn(v.x, v.y); d2[2 * i + 1] = __floats2half2_rn(v.z, v.w);
        }
    } else if (b < 704) {               // selfA1: warp-per-node, 512 blocks x 8 warps
        int w = tid >> 5, lane = tid & 31;
        int n = (b - 192) * 8 + w, nd = nodes[n];
        *(float4*)&sh[w * 128 + lane * 4] = *(const float4*)(u2e + (size_t)nd * 128 + lane * 4);
        __syncwarp();
        float4 acc = *(const float4*)(ab1 + lane * 4);
        const float4* A1b = (const float4*)(A1 + 16384) + lane;   // col block, stride 32 float4/k
        #pragma unroll 8
        for (int k = 0; k < 128; k++) {
            float s = sh[w * 128 + k];
            float4 a4 = __ldg(A1b + k * 32);
            acc.x += s * a4.x; acc.y += s * a4.y; acc.z += s * a4.z; acc.w += s * a4.w;
        }
        *(float4*)(g_selfA1 + (size_t)n * 128 + lane * 4) = acc;
    } else {                            // pack W tables: 128 blocks x 256 = 32768 ids
        int id = (b - 704) * 256 + tid;
        int table, rem, h = 0;
        if (id < 16384)      { table = 1; h = id / 8192; rem = id % 8192; }
        else if (id < 24576) { table = 2; rem = id - 16384; }
        else if (id < 28672) { table = 3; rem = id - 24576; }
        else                 { table = 4; rem = id - 28672; }
        int lane = rem & 31, nb = (rem >> 5) & 15, ks = rem >> 9;
        int n = nb * 8 + (lane >> 2), k0 = ks * 16 + (lane & 3) * 2;
        float v[4];
        #pragma unroll
        for (int j = 0; j < 4; j++) {
            int k = k0 + (j >> 1) * 8 + (j & 1);
            float val;
            if (table == 1)      val = W1[(256 + k) * 256 + h * 128 + n];
            else if (table == 2) val = W2[k * 128 + n];
            else if (table == 3) val = A1[k * 128 + n];
            else                 val = A2[k * 128 + n];
            v[j] = val;
        }
        uint2 fr = make_uint2(pack2(v[0], v[1]), pack2(v[2], v[3]));
        int sidx = ks * 512 + (nb >> 1) * 64 + lane * 2 + (nb & 1);
        if (table == 1)      g_FG1[h * 8192 + sidx] = fr;
        else if (table == 2) g_FG2[sidx] = fr;
        else if (table == 3) g_FG3[sidx] = fr;
        else                 g_FG4[sidx] = fr;
    }
}

// ================= main fused kernel =================
__global__ void __launch_bounds__(512, 1)
k_main(const int* __restrict__ prel, const int* __restrict__ pnbr,
       const int* __restrict__ attrs, const float* __restrict__ u2e,
       const float* __restrict__ b2, const float* __restrict__ ab2,
       const float* __restrict__ A3, const float* __restrict__ ab3,
       float* __restrict__ out) {
    extern __shared__ char sm[];
    const uint32_t sb = smem_u32(sm);
    const int tid = threadIdx.x, wid = tid >> 5, lane = tid & 31;
    const int mg = wid >> 2, ng = wid & 3;
    const int tile = blockIdx.x;

    float* b2s  = (float*)(sm + OFF_B2S);
    float* ab2s = (float*)(sm + OFF_AB2);
    float* A3s  = (float*)(sm + OFF_A3);
    float* SA   = (float*)(sm + OFF_SA);
    float* LG   = (float*)(sm + OFF_LG);
    float* LGP  = (float*)(sm + OFF_LGP);
    float* wgs  = (float*)(sm + OFF_WGT);
    float* OUTa = (float*)(sm + OFF_OUT);
    int2*  RIs  = (int2*)(sm + OFF_RI);
    __half* R12s = (__half*)(sm + OFF_R12);
    char*  XB   = sm + OFF_XB;
    const uint32_t aXB = sb + OFF_XB;

    if (tid < 128) { b2s[tid] = b2[tid]; ab2s[tid] = ab2[tid]; A3s[tid] = A3[tid]; }
    if (tid == 0) *(float*)(sm + OFF_AB3) = ab3[0];
    if (tid < 256) { SA[tid] = g_selfA1[(size_t)tile * 256 + tid]; OUTa[tid] = 0.f; }
    // copy R12h table to smem (33024 B = 2064 uint4)
    {
        const uint4* s = (const uint4*)g_R12h;
        uint4* d = (uint4*)(sm + OFF_R12);
        #pragma unroll
        for (int i = 0; i < 4; i++) d[tid + i * 512] = s[tid + i * 512];
        if (tid < 16) d[2048 + tid] = s[2048 + tid];
    }

    // ---- build X = [ne(128) | ae(128)], 4 thr/row; rel indices -> RIs ----
    {
        int row = tid >> 2, q = tid & 3, p = tile * 128 + row;
        char* XR = XB + row * (XS * 2);
        int nbr = pnbr[p];
        const float4* s = (const float4*)(u2e + (size_t)nbr * 128 + q * 32);
        #pragma unroll
        for (int j = 0; j < 8; j++) {
            float4 v = s[j];
            *(__half2*)(XR + (q * 32 + j * 4) * 2)     = __floats2half2_rn(v.x, v.y);
            *(__half2*)(XR + (q * 32 + j * 4 + 2) * 2) = __floats2half2_rn(v.z, v.w);
        }
        int at[8];
        const int4* ap = (const int4*)(attrs + (size_t)p * 8);
        int4 a0v = ap[0], a1v = ap[1];
        at[0]=a0v.x; at[1]=a0v.y; at[2]=a0v.z; at[3]=a0v.w;
        at[4]=a1v.x; at[5]=a1v.y; at[6]=a1v.z; at[7]=a1v.w;
        float2 acc[16];
        #pragma unroll
        for (int i = 0; i < 16; i++) { acc[i].x = 0.f; acc[i].y = 0.f; }
        uint4 cur[4], nxt[4];
        {
            const uint4* qp = (const uint4*)(g_ua2e_h + (size_t)at[0] * 128) + q * 4;
            #pragma unroll
            for (int j = 0; j < 4; j++) cur[j] = __ldg(qp + j);
        }
        #pragma unroll 1
        for (int a = 0; a < 8; a++) {
            if (a + 1 < 8) {
                const uint4* qp = (const uint4*)(g_ua2e_h + (size_t)at[a + 1] * 128) + q * 4;
                #pragma unroll
                for (int j = 0; j < 4; j++) nxt[j] = __ldg(qp + j);
            }
            #pragma unroll
            for (int j = 0; j < 4; j++) {
                float2 f0 = __half22float2(*(__half2*)&cur[j].x);
                float2 f1 = __half22float2(*(__half2*)&cur[j].y);
                float2 f2 = __half22float2(*(__half2*)&cur[j].z);
                float2 f3 = __half22float2(*(__half2*)&cur[j].w);
                acc[j * 4 + 0].x += f0.x; acc[j * 4 + 0].y += f0.y;
                acc[j * 4 + 1].x += f1.x; acc[j * 4 + 1].y += f1.y;
                acc[j * 4 + 2].x += f2.x; acc[j * 4 + 2].y += f2.y;
                acc[j * 4 + 3].x += f3.x; acc[j * 4 + 3].y += f3.y;
            }
            #pragma unroll
            for (int j = 0; j < 4; j++) cur[j] = nxt[j];
        }
        #pragma unroll
        for (int i = 0; i < 16; i++)
            *(__half2*)(XR + (128 + q * 32 + 2 * i) * 2) = __floats2half2_rn(acc[i].x, acc[i].y);
        if (q == 0) {
            int r0 = prel[p * 2], r1 = prel[p * 2 + 1];
            RIs[row] = make_int2(r0, 32 + r1);
        }
    }
    __syncthreads();

    float acc1[2][4][4], acc2[2][4][4];

    // G1 (dual): X @ W1' -> h1 cols 0-127 (acc1), 128-255 (acc2)
    gemm_dual<256>(aXB, g_FG1, g_FG1 + 8192, acc1, acc2, lane, mg, ng);
    __syncthreads();

    // epilogue1: h1 = relu(acc + R12[r0] + R12[32+r1]) -> fp16 XB cols 0-255
    #pragma unroll
    for (int mf = 0; mf < 2; mf++) {
        int row = mg * 32 + mf * 16 + (lane >> 2);
        int2 ra = RIs[row], rb = RIs[row + 8];
        const __half* Ra0 = R12s + ra.x * 258;
        const __half* Ra1 = R12s + ra.y * 258;
        const __half* Rb0 = R12s + rb.x * 258;
        const __half* Rb1 = R12s + rb.y * 258;
        #pragma unroll
        for (int nt = 0; nt < 4; nt++) {
            int col = ng * 32 + nt * 8 + (lane & 3) * 2;
            float2 pa0 = __half22float2(*(const __half2*)(Ra0 + col));
            float2 pa1 = __half22float2(*(const __half2*)(Ra1 + col));
            float2 pb0 = __half22float2(*(const __half2*)(Rb0 + col));
            float2 pb1 = __half22float2(*(const __half2*)(Rb1 + col));
            *(__half2*)(XB + (row * XS + col) * 2) = __floats2half2_rn(
                fmaxf(acc1[mf][nt][0] + pa0.x + pa1.x, 0.f),
                fmaxf(acc1[mf][nt][1] + pa0.y + pa1.y, 0.f));
            *(__half2*)(XB + ((row + 8) * XS + col) * 2) = __floats2half2_rn(
                fmaxf(acc1[mf][nt][2] + pb0.x + pb1.x, 0.f),
                fmaxf(acc1[mf][nt][3] + pb0.y + pb1.y, 0.f));
            float2 qa0 = __half22float2(*(const __half2*)(Ra0 + col + 128));
            float2 qa1 = __half22float2(*(const __half2*)(Ra1 + col + 128));
            float2 qb0 = __half22float2(*(const __half2*)(Rb0 + col + 128));
            float2 qb1 = __half22float2(*(const __half2*)(Rb1 + col + 128));
            *(__half2*)(XB + (row * XS + col + 128) * 2) = __floats2half2_rn(
                fmaxf(acc2[mf][nt][0] + qa0.x + qa1.x, 0.f),
                fmaxf(acc2[mf][nt][1] + qa0.y + qa1.y, 0.f));
            *(__half2*)(XB + ((row + 8) * XS + col + 128) * 2) = __floats2half2_rn(
                fmaxf(acc2[mf][nt][2] + qb0.x + qb1.x, 0.f),
                fmaxf(acc2[mf][nt][3] + qb0.y + qb1.y, 0.f));
        }
    }
    __syncthreads();
    // G2: h1 @ W2' -> acc2 = h pre-bias (fp32, kept in regs)
    gemm_tile<256>(aXB, g_FG2, acc2, lane, mg, ng);
    __syncthreads();

    // epilogue2: h = relu(acc2 + b2); keep fp32 in acc2, write fp16 XB cols 0-127
    #pragma unroll
    for (int mf = 0; mf < 2; mf++) {
        int row = mg * 32 + mf * 16 + (lane >> 2);
        #pragma unroll
        for (int nt = 0; nt < 4; nt++) {
            int col = ng * 32 + nt * 8 + (lane & 3) * 2;
            float v0 = fmaxf(acc2[mf][nt][0] + b2s[col],     0.f);
            float v1 = fmaxf(acc2[mf][nt][1] + b2s[col + 1], 0.f);
            float v2 = fmaxf(acc2[mf][nt][2] + b2s[col],     0.f);
            float v3 = fmaxf(acc2[mf][nt][3] + b2s[col + 1], 0.f);
            acc2[mf][nt][0] = v0; acc2[mf][nt][1] = v1;
            acc2[mf][nt][2] = v2; acc2[mf][nt][3] = v3;
            *(__half2*)(XB + (row * XS + col) * 2)       = __floats2half2_rn(v0, v1);
            *(__half2*)(XB + ((row + 8) * XS + col) * 2) = __floats2half2_rn(v2, v3);
        }
    }
    __syncthreads();
    // G3: h @ A1top -> acc1
    gemm_tile<128>(aXB, g_FG3, acc1, lane, mg, ng);

    // epilogue3: a1 = relu(acc1 + selfA1[node]) -> fp16 XB cols 128-255
    {
        int node = mg >> 1;
        #pragma unroll
        for (int mf = 0; mf < 2; mf++) {
            int row = mg * 32 + mf * 16 + (lane >> 2);
            #pragma unroll
            for (int nt = 0; nt < 4; nt++) {
                int col = ng * 32 + nt * 8 + (lane & 3) * 2;
                float s0 = SA[node * 128 + col], s1 = SA[node * 128 + col + 1];
                *(__half2*)(XB + (row * XS + col + 128) * 2) =
                    __floats2half2_rn(fmaxf(acc1[mf][nt][0] + s0, 0.f),
                                      fmaxf(acc1[mf][nt][1] + s1, 0.f));
                *(__half2*)(XB + ((row + 8) * XS + col + 128) * 2) =
                    __floats2half2_rn(fmaxf(acc1[mf][nt][2] + s0, 0.f),
                                      fmaxf(acc1[mf][nt][3] + s1, 0.f));
            }
        }
    }
    __syncthreads();
    // G4: a1 @ A2 -> acc1
    gemm_tile<128>(aXB + 256, g_FG4, acc1, lane, mg, ng);

    // epilogue4: a2 = relu(acc1 + ab2); logit partials
    {
        float lp[4] = {0.f, 0.f, 0.f, 0.f};
        #pragma unroll
        for (int mf = 0; mf < 2; mf++)
            #pragma unroll
            for (int nt = 0; nt < 4; nt++) {
                int col = ng * 32 + nt * 8 + (lane & 3) * 2;
                float a30 = A3s[col], a31 = A3s[col + 1];
                float c0 = ab2s[col], c1 = ab2s[col + 1];
                lp[mf * 2 + 0] += fmaxf(acc1[mf][nt][0] + c0, 0.f) * a30
                                + fmaxf(acc1[mf][nt][1] + c1, 0.f) * a31;
                lp[mf * 2 + 1] += fmaxf(acc1[mf][nt][2] + c0, 0.f) * a30
                                + fmaxf(acc1[mf][nt][3] + c1, 0.f) * a31;
            }
        #pragma unroll
        for (int j = 0; j < 4; j++) {
            lp[j] += __shfl_xor_sync(0xffffffffu, lp[j], 1);
            lp[j] += __shfl_xor_sync(0xffffffffu, lp[j], 2);
        }
        if ((lane & 3) == 0) {
            int rbase = mg * 32 + (lane >> 2);
            #pragma unroll
            for (int j = 0; j < 4; j++)
                LGP[ng * 128 + rbase + j * 8] = lp[j];
        }
    }
    __syncthreads();
    if (tid < 128)
        LG[tid] = LGP[tid] + LGP[128 + tid] + LGP[256 + tid] + LGP[384 + tid]
                + *(float*)(sm + OFF_AB3);
    __syncthreads();
    if (wid < 2) {   // softmax per node over its 64 logits
        float a = LG[wid * 64 + lane], b = LG[wid * 64 + 32 + lane];
        float m = fmaxf(a, b);
        #pragma unroll
        for (int o = 16; o; o >>= 1) m = fmaxf(m, __shfl_xor_sync(0xffffffffu, m, o));
        float e1 = __expf(a - m), e2 = __expf(b - m), s = e1 + e2;
        #pragma unroll
        for (int o = 16; o; o >>= 1) s += __shfl_xor_sync(0xffffffffu, s, o);
        wgs[wid * 64 + lane] = e1 / s; wgs[wid * 64 + 32 + lane] = e2 / s;
    }
    __syncthreads();

    // weighted reduce: out[node][col] = sum_r wgs[r] * h[r][col]  (h fp32 in acc2)
    {
        float p[8];
        #pragma unroll
        for (int i = 0; i < 8; i++) p[i] = 0.f;
        #pragma unroll
        for (int mf = 0; mf < 2; mf++) {
            int r0 = mg * 32 + mf * 16 + (lane >> 2);
            float w0 = wgs[r0], w1 = wgs[r0 + 8];
            #pragma unroll
            for (int nt = 0; nt < 4; nt++) {
                p[nt * 2 + 0] += w0 * acc2[mf][nt][0] + w1 * acc2[mf][nt][2];
                p[nt * 2 + 1] += w0 * acc2[mf][nt][1] + w1 * acc2[mf][nt][3];
            }
        }
        #pragma unroll
        for (int i = 0; i < 8; i++) {
            p[i] += __shfl_xor_sync(0xffffffffu, p[i], 4);
            p[i] += __shfl_xor_sync(0xffffffffu, p[i], 8);
            p[i] += __shfl_xor_sync(0xffffffffu, p[i], 16);
        }
        if (lane < 4) {
            int node = mg >> 1;
            #pragma unroll
            for (int i = 0; i < 8; i++) {
                int col = ng * 32 + (i >> 1) * 8 + lane * 2 + (i & 1);
                atomicAdd(&OUTa[node * 128 + col], p[i]);
            }
        }
    }
    __syncthreads();
    if (tid < 256) out[(size_t)tile * 256 + tid] = OUTa[tid];
}

// ================= launch =================
extern "C" void kernel_launch(void* const* d_in, const int* in_sizes, int n_in,
                              void* d_out, int out_size) {
    const int*   nodes = (const int*)  d_in[0];
    const int*   prel  = (const int*)  d_in[1];
    const int*   pnbr  = (const int*)  d_in[2];
    const int*   attrs = (const int*)  d_in[3];
    const float* u2e   = (const float*)d_in[4];
    const float* r2e   = (const float*)d_in[5];
    const float* ua2e  = (const float*)d_in[6];
    const float* W1    = (const float*)d_in[7];
    const float* b1    = (const float*)d_in[8];
    const float* W2    = (const float*)d_in[9];
    const float* b2    = (const float*)d_in[10];
    const float* A1    = (const float*)d_in[11];
    const float* ab1   = (const float*)d_in[12];
    const float* A2    = (const float*)d_in[13];
    const float* ab2   = (const float*)d_in[14];
    const float* A3    = (const float*)d_in[15];
    const float* ab3   = (const float*)d_in[16];
    float* out = (float*)d_out;

    cudaFuncSetAttribute(k_main, cudaFuncAttributeMaxDynamicSharedMemorySize, (int)SMEM_BYTES);

    k_prep<<<832, 256>>>(u2e, ua2e, r2e, W1, b1, nodes, A1, ab1, W2, A2);
    k_main<<<2048, 512, SMEM_BYTES>>>(prel, pnbr, attrs, u2e, b2, ab2, A3, ab3, out);
}

// round 14
// speedup vs baseline: 1.1426x; 1.1386x over previous
#include <cuda_runtime.h>
#include <cuda_fp16.h>
#include <stdint.h>
#include <math.h>

#define DEVFN __device__ __forceinline__

static constexpr int NNODE = 4096, DIM = 128;
static constexpr int NU = 100000, NR = 32, NA = 5000;

// ---- device scratch ----
__device__ __align__(16) __half g_ua2e_h[NA * DIM];
__device__ __align__(16) __half g_R12h  [64 * 258];       // fp16 R12 (stride 258)
__device__ __align__(16) float  g_selfA1[NNODE * DIM];
// B fragments, paired layout: uint4 per (ks, np, lane) = frags for nb=2np, 2np+1
__device__ __align__(16) uint2  g_FG1[2 * 16 * 16 * 32];  // K=256, two n-halves
__device__ __align__(16) uint2  g_FG2[16 * 16 * 32];      // K=256
__device__ __align__(16) uint2  g_FG3[8 * 16 * 32];       // K=128
__device__ __align__(16) uint2  g_FG4[8 * 16 * 32];       // K=128

// ---- smem layout (bytes) ----
static constexpr uint32_t OFF_B2S = 0, OFF_AB2 = 512, OFF_A3 = 1024, OFF_SA = 1536,
    OFF_LG = 2560, OFF_LGP = 3072, OFF_WGT = 5120, OFF_OUT = 5632, OFF_AB3 = 6656,
    OFF_RI = 6672, OFF_R12 = 7696, OFF_XB = 7696 + 33024;  // R12: 64x258 halfs
static constexpr int XS = 264;                        // X stride (halfs), K=256
static constexpr uint32_t SMEM_BYTES = OFF_XB + 128 * XS * 2;   // 108304

// ---- PTX helpers ----
DEVFN uint32_t smem_u32(const void* p) {
    uint32_t a;
    asm("{ .reg .u64 t; cvta.to.shared.u64 t, %1; cvt.u32.u64 %0, t; }" : "=r"(a) : "l"(p));
    return a;
}
DEVFN void ldm4(uint32_t* r, uint32_t a) {
    asm volatile("ldmatrix.sync.aligned.m8n8.x4.shared.b16 {%0,%1,%2,%3}, [%4];"
                 : "=r"(r[0]), "=r"(r[1]), "=r"(r[2]), "=r"(r[3]) : "r"(a));
}
DEVFN void mma16816(float* c, const uint32_t* a, uint32_t b0, uint32_t b1) {
    asm volatile("mma.sync.aligned.m16n8k16.row.col.f32.f16.f16.f32 "
                 "{%0,%1,%2,%3}, {%4,%5,%6,%7}, {%8,%9}, {%0,%1,%2,%3};"
                 : "+f"(c[0]), "+f"(c[1]), "+f"(c[2]), "+f"(c[3])
                 : "r"(a[0]), "r"(a[1]), "r"(a[2]), "r"(a[3]), "r"(b0), "r"(b1));
}
DEVFN uint32_t pack2(float a, float b) {
    __half2 h = __floats2half2_rn(a, b);
    return *(uint32_t*)&h;
}

// single GEMM, paired-uint4 B fragments, register double-buffered prefetch
// 16 warps 4x4: mg 32 rows, ng 32 cols (4 nt)
template<int K>
DEVFN void gemm_tile(uint32_t aXbase, const uint2* __restrict__ F,
                     float (&acc)[2][4][4], int lane, int mg, int ng) {
    constexpr int KS = K / 16;
    uint32_t aA = aXbase + (uint32_t)((mg * 32 + ((lane >> 3) & 1) * 8 + (lane & 7)) * XS
                                      + (lane >> 4) * 8) * 2;
    const uint4* Fw = (const uint4*)F + (ng * 2) * 32 + lane;
    #pragma unroll
    for (int m = 0; m < 2; m++)
        #pragma unroll
        for (int n = 0; n < 4; n++)
            #pragma unroll
            for (int e = 0; e < 4; e++) acc[m][n][e] = 0.f;
    uint4 bf[2], bn[2];
    #pragma unroll
    for (int j = 0; j < 2; j++) bf[j] = __ldg(Fw + j * 32);
    #pragma unroll 1
    for (int ks = 0; ks < KS; ks++) {
        if (ks + 1 < KS) {
            #pragma unroll
            for (int j = 0; j < 2; j++) bn[j] = __ldg(Fw + (ks + 1) * 256 + j * 32);
        }
        uint32_t a0[4], a1[4];
        ldm4(a0, aA + ks * 32);
        ldm4(a1, aA + 16 * XS * 2 + ks * 32);
        #pragma unroll
        for (int j = 0; j < 2; j++) {
            mma16816(acc[0][2 * j],     a0, bf[j].x, bf[j].y);
            mma16816(acc[1][2 * j],     a1, bf[j].x, bf[j].y);
            mma16816(acc[0][2 * j + 1], a0, bf[j].z, bf[j].w);
            mma16816(acc[1][2 * j + 1], a1, bf[j].z, bf[j].w);
        }
        #pragma unroll
        for (int j = 0; j < 2; j++) bf[j] = bn[j];
    }
}

// dual GEMM (shared A fragments, two B tables), paired + prefetched
template<int K>
DEVFN void gemm_dual(uint32_t aXbase, const uint2* __restrict__ F0,
                     const uint2* __restrict__ F1,
                     float (&acc1)[2][4][4], float (&acc2)[2][4][4],
                     int lane, int mg, int ng) {
    constexpr int KS = K / 16;
    uint32_t aA = aXbase + (uint32_t)((mg * 32 + ((lane >> 3) & 1) * 8 + (lane & 7)) * XS
                                      + (lane >> 4) * 8) * 2;
    const uint4* Fw0 = (const uint4*)F0 + (ng * 2) * 32 + lane;
    const uint4* Fw1 = (const uint4*)F1 + (ng * 2) * 32 + lane;
    #pragma unroll
    for (int m = 0; m < 2; m++)
        #pragma unroll
        for (int n = 0; n < 4; n++)
            #pragma unroll
            for (int e = 0; e < 4; e++) { acc1[m][n][e] = 0.f; acc2[m][n][e] = 0.f; }
    uint4 bf0[2], bf1[2], bn0[2], bn1[2];
    #pragma unroll
    for (int j = 0; j < 2; j++) { bf0[j] = __ldg(Fw0 + j * 32); bf1[j] = __ldg(Fw1 + j * 32); }
    #pragma unroll 1
    for (int ks = 0; ks < KS; ks++) {
        if (ks + 1 < KS) {
            #pragma unroll
            for (int j = 0; j < 2; j++) {
                bn0[j] = __ldg(Fw0 + (ks + 1) * 256 + j * 32);
                bn1[j] = __ldg(Fw1 + (ks + 1) * 256 + j * 32);
            }
        }
        uint32_t a0[4], a1[4];
        ldm4(a0, aA + ks * 32);
        ldm4(a1, aA + 16 * XS * 2 + ks * 32);
        #pragma unroll
        for (int j = 0; j < 2; j++) {
            mma16816(acc1[0][2 * j],     a0, bf0[j].x, bf0[j].y);
            mma16816(acc1[1][2 * j],     a1, bf0[j].x, bf0[j].y);
            mma16816(acc1[0][2 * j + 1], a0, bf0[j].z, bf0[j].w);
            mma16816(acc1[1][2 * j + 1], a1, bf0[j].z, bf0[j].w);
            mma16816(acc2[0][2 * j],     a0, bf1[j].x, bf1[j].y);
            mma16816(acc2[1][2 * j],     a1, bf1[j].x, bf1[j].y);
            mma16816(acc2[0][2 * j + 1], a0, bf1[j].z, bf1[j].w);
            mma16816(acc2[1][2 * j + 1], a1, bf1[j].z, bf1[j].w);
        }
        #pragma unroll
        for (int j = 0; j < 2; j++) { bf0[j] = bn0[j]; bf1[j] = bn1[j]; }
    }
}

// ===== SINGLE prepass kernel: r12+R12h (64) || ua2e cvt (128) || selfA1 (512) || pack (128) =====
__global__ void k_prep(const float* __restrict__ u2e, const float* __restrict__ ua2e,
                       const float* __restrict__ r2e, const float* __restrict__ W1,
                       const float* __restrict__ b1, const int* __restrict__ nodes,
                       const float* __restrict__ A1, const float* __restrict__ ab1,
                       const float* __restrict__ W2, const float* __restrict__ A2) {
    __shared__ float sh[8 * 128];
    int b = blockIdx.x, tid = threadIdx.x;
    if (b < 64) {                       // r12: b = t*32+i -> writes fp16 R12h row directly
        int t = b >> 5, i = b & 31, c = tid;
        if (c < 128) sh[c] = r2e[i * 128 + c];
        __syncthreads();
        float acc = (t == 0) ? b1[c] : 0.f;
        #pragma unroll 4
        for (int k = 0; k < 128; k++) acc += sh[k] * W1[(t * 128 + k) * 256 + c];
        int r = t * 32 + i;
        g_R12h[r * 258 + c] = __float2half_rn(acc);
        if (c < 2) g_R12h[r * 258 + 256 + c] = __ushort_as_half((unsigned short)0);
    } else if (b < 192) {               // ua2e convert (2.56 MB), 128 blocks
        int st = 128 * 256, t0 = (b - 64) * 256 + tid;
        const float4* s2 = (const float4*)ua2e;  __half2* d2 = (__half2*)g_ua2e_h;
        for (int i = t0; i < NA * DIM / 4; i += st) {
            float4 v = s2[i];
            d2[2 * i] = __floats2half2_rn(v.x, v.y); d2[2 * i + 1] = __floats2half2_rn(v.z, v.w);
        }
    } else if (b < 704) {               // selfA1: warp-per-node, 512 blocks x 8 warps
        int w = tid >> 5, lane = tid & 31;
        int n = (b - 192) * 8 + w, nd = nodes[n];
        *(float4*)&sh[w * 128 + lane * 4] = *(const float4*)(u2e + (size_t)nd * 128 + lane * 4);
        __syncwarp();
        float4 acc = *(const float4*)(ab1 + lane * 4);
        const float4* A1b = (const float4*)(A1 + 16384) + lane;   // col block, stride 32 float4/k
        #pragma unroll 8
        for (int k = 0; k < 128; k++) {
            float s = sh[w * 128 + k];
            float4 a4 = __ldg(A1b + k * 32);
            acc.x += s * a4.x; acc.y += s * a4.y; acc.z += s * a4.z; acc.w += s * a4.w;
        }
        *(float4*)(g_selfA1 + (size_t)n * 128 + lane * 4) = acc;
    } else {                            // pack W tables: 128 blocks x 256 = 32768 ids
        int id = (b - 704) * 256 + tid;
        int table, rem, h = 0;
        if (id < 16384)      { table = 1; h = id / 8192; rem = id % 8192; }
        else if (id < 24576) { table = 2; rem = id - 16384; }
        else if (id < 28672) { table = 3; rem = id - 24576; }
        else                 { table = 4; rem = id - 28672; }
        int lane = rem & 31, nb = (rem >> 5) & 15, ks = rem >> 9;
        int n = nb * 8 + (lane >> 2), k0 = ks * 16 + (lane & 3) * 2;
        float v[4];
        #pragma unroll
        for (int j = 0; j < 4; j++) {
            int k = k0 + (j >> 1) * 8 + (j & 1);
            float val;
            if (table == 1)      val = W1[(256 + k) * 256 + h * 128 + n];
            else if (table == 2) val = W2[k * 128 + n];
            else if (table == 3) val = A1[k * 128 + n];
            else                 val = A2[k * 128 + n];
            v[j] = val;
        }
        uint2 fr = make_uint2(pack2(v[0], v[1]), pack2(v[2], v[3]));
        int sidx = ks * 512 + (nb >> 1) * 64 + lane * 2 + (nb & 1);
        if (table == 1)      g_FG1[h * 8192 + sidx] = fr;
        else if (table == 2) g_FG2[sidx] = fr;
        else if (table == 3) g_FG3[sidx] = fr;
        else                 g_FG4[sidx] = fr;
    }
}

// ================= main fused kernel =================
__global__ void __launch_bounds__(512, 1)
k_main(const int* __restrict__ prel, const int* __restrict__ pnbr,
       const int* __restrict__ attrs, const float* __restrict__ u2e,
       const float* __restrict__ b2, const float* __restrict__ ab2,
       const float* __restrict__ A3, const float* __restrict__ ab3,
       float* __restrict__ out) {
    extern __shared__ char sm[];
    const uint32_t sb = smem_u32(sm);
    const int tid = threadIdx.x, wid = tid >> 5, lane = tid & 31;
    const int mg = wid >> 2, ng = wid & 3;
    const int tile = blockIdx.x;

    float* b2s  = (float*)(sm + OFF_B2S);
    float* ab2s = (float*)(sm + OFF_AB2);
    float* A3s  = (float*)(sm + OFF_A3);
    float* SA   = (float*)(sm + OFF_SA);
    float* LG   = (float*)(sm + OFF_LG);
    float* LGP  = (float*)(sm + OFF_LGP);
    float* wgs  = (float*)(sm + OFF_WGT);
    float* OUTa = (float*)(sm + OFF_OUT);
    int2*  RIs  = (int2*)(sm + OFF_RI);
    __half* R12s = (__half*)(sm + OFF_R12);
    char*  XB   = sm + OFF_XB;
    const uint32_t aXB = sb + OFF_XB;

    if (tid < 128) { b2s[tid] = b2[tid]; ab2s[tid] = ab2[tid]; A3s[tid] = A3[tid]; }
    if (tid == 0) *(float*)(sm + OFF_AB3) = ab3[0];
    if (tid < 256) { SA[tid] = g_selfA1[(size_t)tile * 256 + tid]; OUTa[tid] = 0.f; }
    // copy R12h table to smem (33024 B = 2064 uint4)
    {
        const uint4* s = (const uint4*)g_R12h;
        uint4* d = (uint4*)(sm + OFF_R12);
        #pragma unroll
        for (int i = 0; i < 4; i++) d[tid + i * 512] = s[tid + i * 512];
        if (tid < 16) d[2048 + tid] = s[2048 + tid];
    }

    // ---- build X = [ne(128) | ae(128)]: warp-per-row coalesced gather, 8 rows/warp ----
    {
        const int rbase = wid * 8;
        #pragma unroll 1
        for (int s8 = 0; s8 < 8; s8++) {
            int row = rbase + s8, p = tile * 128 + row;
            char* XR = XB + row * (XS * 2);
            int nbr = __ldg(pnbr + p);
            // ne: whole 512B u2e row, lane -> float4 (coalesced), convert to 4 halfs
            float4 v = __ldg((const float4*)(u2e + (size_t)nbr * 128) + lane);
            uint2 ne = make_uint2(pack2(v.x, v.y), pack2(v.z, v.w));
            *(uint2*)(XR + lane * 8) = ne;
            // ae: 8 attr rows, lane -> uint2 (4 halfs, coalesced 256B/row)
            const int4* ap = (const int4*)(attrs + (size_t)p * 8);
            int4 a0v = __ldg(ap), a1v = __ldg(ap + 1);
            int at[8];
            at[0]=a0v.x; at[1]=a0v.y; at[2]=a0v.z; at[3]=a0v.w;
            at[4]=a1v.x; at[5]=a1v.y; at[6]=a1v.z; at[7]=a1v.w;
            uint2 d[8];
            #pragma unroll
            for (int a = 0; a < 8; a++)
                d[a] = __ldg((const uint2*)(g_ua2e_h + (size_t)at[a] * 128) + lane);
            float2 s0 = make_float2(0.f, 0.f), s1 = make_float2(0.f, 0.f);
            #pragma unroll
            for (int a = 0; a < 8; a++) {
                float2 f0 = __half22float2(*(__half2*)&d[a].x);
                float2 f1 = __half22float2(*(__half2*)&d[a].y);
                s0.x += f0.x; s0.y += f0.y; s1.x += f1.x; s1.y += f1.y;
            }
            *(uint2*)(XR + 256 + lane * 8) = make_uint2(pack2(s0.x, s0.y), pack2(s1.x, s1.y));
            if (lane == 0) {
                int r0 = __ldg(prel + p * 2), r1 = __ldg(prel + p * 2 + 1);
                RIs[row] = make_int2(r0, 32 + r1);
            }
        }
    }
    __syncthreads();

    float acc1[2][4][4], acc2[2][4][4];

    // G1 (dual): X @ W1' -> h1 cols 0-127 (acc1), 128-255 (acc2)
    gemm_dual<256>(aXB, g_FG1, g_FG1 + 8192, acc1, acc2, lane, mg, ng);
    __syncthreads();

    // epilogue1: h1 = relu(acc + R12[r0] + R12[32+r1]) -> fp16 XB cols 0-255
    #pragma unroll
    for (int mf = 0; mf < 2; mf++) {
        int row = mg * 32 + mf * 16 + (lane >> 2);
        int2 ra = RIs[row], rb = RIs[row + 8];
        const __half* Ra0 = R12s + ra.x * 258;
        const __half* Ra1 = R12s + ra.y * 258;
        const __half* Rb0 = R12s + rb.x * 258;
        const __half* Rb1 = R12s + rb.y * 258;
        #pragma unroll
        for (int nt = 0; nt < 4; nt++) {
            int col = ng * 32 + nt * 8 + (lane & 3) * 2;
            float2 pa0 = __half22float2(*(const __half2*)(Ra0 + col));
            float2 pa1 = __half22float2(*(const __half2*)(Ra1 + col));
            float2 pb0 = __half22float2(*(const __half2*)(Rb0 + col));
            float2 pb1 = __half22float2(*(const __half2*)(Rb1 + col));
            *(__half2*)(XB + (row * XS + col) * 2) = __floats2half2_rn(
                fmaxf(acc1[mf][nt][0] + pa0.x + pa1.x, 0.f),
                fmaxf(acc1[mf][nt][1] + pa0.y + pa1.y, 0.f));
            *(__half2*)(XB + ((row + 8) * XS + col) * 2) = __floats2half2_rn(
                fmaxf(acc1[mf][nt][2] + pb0.x + pb1.x, 0.f),
                fmaxf(acc1[mf][nt][3] + pb0.y + pb1.y, 0.f));
            float2 qa0 = __half22float2(*(const __half2*)(Ra0 + col + 128));
            float2 qa1 = __half22float2(*(const __half2*)(Ra1 + col + 128));
            float2 qb0 = __half22float2(*(const __half2*)(Rb0 + col + 128));
            float2 qb1 = __half22float2(*(const __half2*)(Rb1 + col + 128));
            *(__half2*)(XB + (row * XS + col + 128) * 2) = __floats2half2_rn(
                fmaxf(acc2[mf][nt][0] + qa0.x + qa1.x, 0.f),
                fmaxf(acc2[mf][nt][1] + qa0.y + qa1.y, 0.f));
            *(__half2*)(XB + ((row + 8) * XS + col + 128) * 2) = __floats2half2_rn(
                fmaxf(acc2[mf][nt][2] + qb0.x + qb1.x, 0.f),
                fmaxf(acc2[mf][nt][3] + qb0.y + qb1.y, 0.f));
        }
    }
    __syncthreads();
    // G2: h1 @ W2' -> acc2 = h pre-bias (fp32, kept in regs)
    gemm_tile<256>(aXB, g_FG2, acc2, lane, mg, ng);
    __syncthreads();

    // epilogue2: h = relu(acc2 + b2); keep fp32 in acc2, write fp16 XB cols 0-127
    #pragma unroll
    for (int mf = 0; mf < 2; mf++) {
        int row = mg * 32 + mf * 16 + (lane >> 2);
        #pragma unroll
        for (int nt = 0; nt < 4; nt++) {
            int col = ng * 32 + nt * 8 + (lane & 3) * 2;
            float v0 = fmaxf(acc2[mf][nt][0] + b2s[col],     0.f);
            float v1 = fmaxf(acc2[mf][nt][1] + b2s[col + 1], 0.f);
            float v2 = fmaxf(acc2[mf][nt][2] + b2s[col],     0.f);
            float v3 = fmaxf(acc2[mf][nt][3] + b2s[col + 1], 0.f);
            acc2[mf][nt][0] = v0; acc2[mf][nt][1] = v1;
            acc2[mf][nt][2] = v2; acc2[mf][nt][3] = v3;
            *(__half2*)(XB + (row * XS + col) * 2)       = __floats2half2_rn(v0, v1);
            *(__half2*)(XB + ((row + 8) * XS + col) * 2) = __floats2half2_rn(v2, v3);
        }
    }
    __syncthreads();
    // G3: h @ A1top -> acc1
    gemm_tile<128>(aXB, g_FG3, acc1, lane, mg, ng);

    // epilogue3: a1 = relu(acc1 + selfA1[node]) -> fp16 XB cols 128-255
    {
        int node = mg >> 1;
        #pragma unroll
        for (int mf = 0; mf < 2; mf++) {
            int row = mg * 32 + mf * 16 + (lane >> 2);
            #pragma unroll
            for (int nt = 0; nt < 4; nt++) {
                int col = ng * 32 + nt * 8 + (lane & 3) * 2;
                float s0 = SA[node * 128 + col], s1 = SA[node * 128 + col + 1];
                *(__half2*)(XB + (row * XS + col + 128) * 2) =
                    __floats2half2_rn(fmaxf(acc1[mf][nt][0] + s0, 0.f),
                                      fmaxf(acc1[mf][nt][1] + s1, 0.f));
                *(__half2*)(XB + ((row + 8) * XS + col + 128) * 2) =
                    __floats2half2_rn(fmaxf(acc1[mf][nt][2] + s0, 0.f),
                                      fmaxf(acc1[mf][nt][3] + s1, 0.f));
            }
        }
    }
    __syncthreads();
    // G4: a1 @ A2 -> acc1
    gemm_tile<128>(aXB + 256, g_FG4, acc1, lane, mg, ng);

    // epilogue4: a2 = relu(acc1 + ab2); logit partials
    {
        float lp[4] = {0.f, 0.f, 0.f, 0.f};
        #pragma unroll
        for (int mf = 0; mf < 2; mf++)
            #pragma unroll
            for (int nt = 0; nt < 4; nt++) {
                int col = ng * 32 + nt * 8 + (lane & 3) * 2;
                float a30 = A3s[col], a31 = A3s[col + 1];
                float c0 = ab2s[col], c1 = ab2s[col + 1];
                lp[mf * 2 + 0] += fmaxf(acc1[mf][nt][0] + c0, 0.f) * a30
                                + fmaxf(acc1[mf][nt][1] + c1, 0.f) * a31;
                lp[mf * 2 + 1] += fmaxf(acc1[mf][nt][2] + c0, 0.f) * a30
                                + fmaxf(acc1[mf][nt][3] + c1, 0.f) * a31;
            }
        #pragma unroll
        for (int j = 0; j < 4; j++) {
            lp[j] += __shfl_xor_sync(0xffffffffu, lp[j], 1);
            lp[j] += __shfl_xor_sync(0xffffffffu, lp[j], 2);
        }
        if ((lane & 3) == 0) {
            int rbase = mg * 32 + (lane >> 2);
            #pragma unroll
            for (int j = 0; j < 4; j++)
                LGP[ng * 128 + rbase + j * 8] = lp[j];
        }
    }
    __syncthreads();
    if (tid < 128)
        LG[tid] = LGP[tid] + LGP[128 + tid] + LGP[256 + tid] + LGP[384 + tid]
                + *(float*)(sm + OFF_AB3);
    __syncthreads();
    if (wid < 2) {   // softmax per node over its 64 logits
        float a = LG[wid * 64 + lane], b = LG[wid * 64 + 32 + lane];
        float m = fmaxf(a, b);
        #pragma unroll
        for (int o = 16; o; o >>= 1) m = fmaxf(m, __shfl_xor_sync(0xffffffffu, m, o));
        float e1 = __expf(a - m), e2 = __expf(b - m), s = e1 + e2;
        #pragma unroll
        for (int o = 16; o; o >>= 1) s += __shfl_xor_sync(0xffffffffu, s, o);
        wgs[wid * 64 + lane] = e1 / s; wgs[wid * 64 + 32 + lane] = e2 / s;
    }
    __syncthreads();

    // weighted reduce: out[node][col] = sum_r wgs[r] * h[r][col]  (h fp32 in acc2)
    {
        float p[8];
        #pragma unroll
        for (int i = 0; i < 8; i++) p[i] = 0.f;
        #pragma unroll
        for (int mf = 0; mf < 2; mf++) {
            int r0 = mg * 32 + mf * 16 + (lane >> 2);
            float w0 = wgs[r0], w1 = wgs[r0 + 8];
            #pragma unroll
            for (int nt = 0; nt < 4; nt++) {
                p[nt * 2 + 0] += w0 * acc2[mf][nt][0] + w1 * acc2[mf][nt][2];
                p[nt * 2 + 1] += w0 * acc2[mf][nt][1] + w1 * acc2[mf][nt][3];
            }
        }
        #pragma unroll
        for (int i = 0; i < 8; i++) {
            p[i] += __shfl_xor_sync(0xffffffffu, p[i], 4);
            p[i] += __shfl_xor_sync(0xffffffffu, p[i], 8);
            p[i] += __shfl_xor_sync(0xffffffffu, p[i], 16);
        }
        if (lane < 4) {
            int node = mg >> 1;
            #pragma unroll
            for (int i = 0; i < 8; i++) {
                int col = ng * 32 + (i >> 1) * 8 + lane * 2 + (i & 1);
                atomicAdd(&OUTa[node * 128 + col], p[i]);
            }
        }
    }
    __syncthreads();
    if (tid < 256) out[(size_t)tile * 256 + tid] = OUTa[tid];
}

// ================= launch =================
extern "C" void kernel_launch(void* const* d_in, const int* in_sizes, int n_in,
                              void* d_out, int out_size) {
    const int*   nodes = (const int*)  d_in[0];
    const int*   prel  = (const int*)  d_in[1];
    const int*   pnbr  = (const int*)  d_in[2];
    const int*   attrs = (const int*)  d_in[3];
    const float* u2e   = (const float*)d_in[4];
    const float* r2e   = (const float*)d_in[5];
    const float* ua2e  = (const float*)d_in[6];
    const float* W1    = (const float*)d_in[7];
    const float* b1    = (const float*)d_in[8];
    const float* W2    = (const float*)d_in[9];
    const float* b2    = (const float*)d_in[10];
    const float* A1    = (const float*)d_in[11];
    const float* ab1   = (const float*)d_in[12];
    const float* A2    = (const float*)d_in[13];
    const float* ab2   = (const float*)d_in[14];
    const float* A3    = (const float*)d_in[15];
    const float* ab3   = (const float*)d_in[16];
    float* out = (float*)d_out;

    cudaFuncSetAttribute(k_main, cudaFuncAttributeMaxDynamicSharedMemorySize, (int)SMEM_BYTES);

    k_prep<<<832, 256>>>(u2e, ua2e, r2e, W1, b1, nodes, A1, ab1, W2, A2);
    k_main<<<2048, 512, SMEM_BYTES>>>(prel, pnbr, attrs, u2e, b2, ab2, A3, ab3, out);
}